// round 6
// baseline (speedup 1.0000x reference)
#include <cuda_runtime.h>
#include <math.h>

// ---------------------------------------------------------------------------
// Static device scratch (allocation-free rule). Zero-initialized at load.
// ---------------------------------------------------------------------------
#define MAX_M 50432
#define LC    256      // chunk length for the linear G/I scans (power of 2)
#define LSEG  800      // segment length for the v-relaxation (multiple of 32)

__device__ float  d_Sg[MAX_M];        // per-row weighted spike sums
__device__ float  d_Si[MAX_M];
__device__ float  d_Gl[MAX_M];        // chunk-local forced responses
__device__ float  d_Il[MAX_M];
__device__ float  d_Gfe[256];         // chunk forced exit values
__device__ float  d_Ife[256];
__device__ double d_GstD[256];        // chunk-start carries (double)
__device__ double d_IstD[256];
__device__ float2 d_cb[MAX_M];        // per-step (c, b) coefficients
__device__ float  g_ent[2][66];       // segment entry values, ping-pong
__device__ int    g_chg[2];           // per-parity "any exit changed" flags
__device__ int    g_bar_count;        // global barrier
__device__ int    g_bar_sense;

// ---------------------------------------------------------------------------
// Kernel 1: per-row weighted sums (L2-resident stream, ~4 us).
// ---------------------------------------------------------------------------
__global__ void rowdot_kernel(const float* __restrict__ spikes,
                              const float* __restrict__ w,
                              const float* __restrict__ vrev,
                              int m, int n) {
    __shared__ float4 s_aw[128];
    __shared__ float4 s_wv[128];

    const int tid  = threadIdx.x;
    const int lane = tid & 31;
    const int wrp  = tid >> 5;
    const int nv4  = n >> 2;

    for (int j = tid; j < nv4; j += blockDim.x) {
        float4 wj = reinterpret_cast<const float4*>(w)[j];
        float4 vj = reinterpret_cast<const float4*>(vrev)[j];
        float4 aw = make_float4(fabsf(wj.x), fabsf(wj.y), fabsf(wj.z), fabsf(wj.w));
        s_aw[j] = aw;
        s_wv[j] = make_float4(__fmul_rn(vj.x, aw.x), __fmul_rn(vj.y, aw.y),
                              __fmul_rn(vj.z, aw.z), __fmul_rn(vj.w, aw.w));
    }
    __syncthreads();

    const int row = blockIdx.x * (blockDim.x >> 5) + wrp;
    if (row >= m) return;

    const float4* rp = reinterpret_cast<const float4*>(spikes + (size_t)row * n);
    float accg = 0.0f, acci = 0.0f;
    for (int j = lane; j < nv4; j += 32) {
        float4 s  = rp[j];
        float4 aw = s_aw[j];
        float4 wv = s_wv[j];
        accg = fmaf(s.x, aw.x, accg); accg = fmaf(s.y, aw.y, accg);
        accg = fmaf(s.z, aw.z, accg); accg = fmaf(s.w, aw.w, accg);
        acci = fmaf(s.x, wv.x, acci); acci = fmaf(s.y, wv.y, acci);
        acci = fmaf(s.z, wv.z, acci); acci = fmaf(s.w, wv.w, acci);
    }
    for (int j = (nv4 << 2) + lane; j < n; j += 32) {
        float aw = fabsf(w[j]);
        float sv = spikes[(size_t)row * n + j];
        accg = fmaf(sv, aw, accg);
        acci = fmaf(sv, __fmul_rn(vrev[j], aw), acci);
    }

    #pragma unroll
    for (int o = 16; o > 0; o >>= 1) {
        accg += __shfl_down_sync(0xffffffffu, accg, o);
        acci += __shfl_down_sync(0xffffffffu, acci, o);
    }
    if (lane == 0) {
        d_Sg[row] = accg;
        d_Si[row] = acci;
    }
}

// ---------------------------------------------------------------------------
// Kernel 2: chunk-local forced responses of the linear traces, one warp per
// 256-step chunk, exact reference op order within the chunk:
//   G[k+1] = (G[k] + Sg[k]) * decay, starting from 0 at the chunk base.
// Stores Gloc/Iloc per index and the chunk forced-exit values.
// ---------------------------------------------------------------------------
__global__ void chains_kernel(int nchunk) {
    const int c    = blockIdx.x;
    const int lane = threadIdx.x;
    const int base = c * LC;
    const float d  = expf(-0.1f);

    float sg[8], si[8];
    #pragma unroll
    for (int q = 0; q < 8; ++q) {
        sg[q] = d_Sg[base + q * 32 + lane];   // pad region is static zero
        si[q] = d_Si[base + q * 32 + lane];
    }

    float G = 0.0f, I = 0.0f;
    #pragma unroll
    for (int q = 0; q < 8; ++q) {
        float gs = 0.0f, is = 0.0f;
        #pragma unroll
        for (int k = 0; k < 32; ++k) {
            const float sgk = __shfl_sync(0xffffffffu, sg[q], k);
            const float sik = __shfl_sync(0xffffffffu, si[q], k);
            if (k == lane) { gs = G; is = I; }            // value AT index
            G = __fmul_rn(__fadd_rn(G, sgk), d);
            I = __fmul_rn(__fadd_rn(I, sik), d);
        }
        d_Gl[base + q * 32 + lane] = gs;
        d_Il[base + q * 32 + lane] = is;
    }
    if (lane == 0) { d_Gfe[c] = G; d_Ife[c] = I; }
}

// ---------------------------------------------------------------------------
// Kernel 3: chunk carries in double (serial over ~196 chunks, cheap):
//   H[c+1] = H[c]*decay^LC + forced_exit[c],  G_start[c] = H[c]
// decay^LC computed from log of the ROUNDED float decay (faithful to g^k).
// ---------------------------------------------------------------------------
__global__ void carry_kernel(int nchunk) {
    const double lg = log((double)expf(-0.1f));
    const double D  = exp((double)LC * lg);
    double Hg = 0.0, Hi = 0.0;
    for (int c = 0; c < nchunk; ++c) {
        d_GstD[c] = Hg;
        d_IstD[c] = Hi;
        Hg = Hg * D + (double)d_Gfe[c];
        Hi = Hi * D + (double)d_Ife[c];
    }
}

// ---------------------------------------------------------------------------
// Kernel 4: recombine G,I and emit per-step (c,b); reset relaxation state.
//   G_i = Gloc_i + Gst_chunk * g^off   (double combine, single final round)
//   a = 0.001*(1+G); c = 1-a; b = 0.001*I   (reference expression order)
// Pads [m-1, total) with identity steps (c=1, b=0).
// ---------------------------------------------------------------------------
__global__ void combine_kernel(float* __restrict__ vtr, int m, int total) {
    const int i = blockIdx.x * blockDim.x + threadIdx.x;
    if (i >= total) return;

    if (i < 66) { g_ent[0][i] = 0.0f; g_ent[1][i] = 0.0f; }
    if (i == 0) {
        g_chg[0] = 0; g_chg[1] = 0;
        g_bar_count = 0; g_bar_sense = 0;
        vtr[0] = 0.0f;
    }

    if (i >= m - 1) { d_cb[i] = make_float2(1.0f, 0.0f); return; }

    const double lg  = log((double)expf(-0.1f));
    const int    c   = i >> 8;           // LC = 256
    const int    off = i & 255;
    const double P   = exp((double)off * lg);

    const float G = (float)((double)d_Gl[i] + d_GstD[c] * P);
    const float I = (float)((double)d_Il[i] + d_IstD[c] * P);

    const float a  = __fmul_rn(0.001f, __fadd_rn(1.0f, G));
    const float cf = __fadd_rn(1.0f, -a);
    const float b  = __fmul_rn(0.001f, I);
    d_cb[i] = make_float2(cf, b);
}

// ---------------------------------------------------------------------------
// Kernel 5: Jacobi relaxation of the v recurrence to its exact fixed point.
// S segments x LSEG steps; each one-warp block runs its segment with the
// BIT-EXACT reference step order each sweep:
//   u = rn(rn(v*c) + b);  v' = (v < 1) ? u : 0
// Entries ping-pong through g_ent; converged when no exit changes bitwise
// (unique fixed point anchored at v=0 => exact forward-substitution result).
// Hard cap 80 sweeps >= S guarantees exactness in the worst case.
// ---------------------------------------------------------------------------
#define STEP(cc, bb, IDX) do {                                   \
    const float u_ = __fadd_rn(__fmul_rn(v, (cc)), (bb));        \
    v = (v < 1.0f) ? u_ : 0.0f;                                  \
    if ((IDX) == lane) vout = v;                                 \
} while (0)

#define GROUP8(Q) {                                              \
    const float4 n0_ = s4[pb + ((Q) + 1) * 4 + 0];               \
    const float4 n1_ = s4[pb + ((Q) + 1) * 4 + 1];               \
    const float4 n2_ = s4[pb + ((Q) + 1) * 4 + 2];               \
    const float4 n3_ = s4[pb + ((Q) + 1) * 4 + 3];               \
    STEP(p0.x, p0.y, (Q) * 8 + 0); STEP(p0.z, p0.w, (Q) * 8 + 1);\
    STEP(p1.x, p1.y, (Q) * 8 + 2); STEP(p1.z, p1.w, (Q) * 8 + 3);\
    STEP(p2.x, p2.y, (Q) * 8 + 4); STEP(p2.z, p2.w, (Q) * 8 + 5);\
    STEP(p3.x, p3.y, (Q) * 8 + 6); STEP(p3.z, p3.w, (Q) * 8 + 7);\
    p0 = n0_; p1 = n1_; p2 = n2_; p3 = n3_; }

__global__ void sweep_kernel(float* __restrict__ vtr, int m) {
    __shared__ float2 scb[LSEG + 8];     // +8: prefetch overread pad

    const int k    = blockIdx.x;
    const int lane = threadIdx.x;
    const int S    = gridDim.x;
    const int base = k * LSEG;

    // stage this segment's (c,b) into smem once
    float4*       s4 = reinterpret_cast<float4*>(scb);
    const float4* g4 = reinterpret_cast<const float4*>(d_cb + base);
    for (int idx = lane; idx < (LSEG + 8) / 2; idx += 32) s4[idx] = g4[idx];
    __syncwarp();

    float prev_exit = 0.0f;
    int   my_sense  = 0;

    for (int s = 0; s < 80; ++s) {
        const int cur = s & 1, nxt = cur ^ 1;
        float v = ((volatile float*)g_ent[cur])[k];

        float4 p0 = s4[0], p1 = s4[1], p2 = s4[2], p3 = s4[3];
        for (int t = 0; t < LSEG / 32; ++t) {
            float vout = 0.0f;
            const int pb = t * 16;
            GROUP8(0); GROUP8(1); GROUP8(2); GROUP8(3);
            const int i = base + t * 32 + lane + 1;
            if (i < m) vtr[i] = vout;
        }

        const int changed = (__float_as_int(v) != __float_as_int(prev_exit));
        prev_exit = v;
        my_sense ^= 1;
        int chgv = 0;
        if (lane == 0) {
            g_ent[nxt][k + 1] = v;
            if (changed) atomicOr(&g_chg[cur], 1);
            __threadfence();
            if (atomicAdd(&g_bar_count, 1) == S - 1) {   // last arriver
                g_bar_count = 0;
                g_chg[nxt]  = 0;                         // slot for sweep s+1
                __threadfence();
                g_bar_sense = my_sense;                  // release
            } else {
                while (*((volatile int*)&g_bar_sense) != my_sense) { }
            }
            __threadfence();
            chgv = *((volatile int*)&g_chg[cur]);
        }
        __syncwarp();
        chgv = __shfl_sync(0xffffffffu, chgv, 0);
        if (s >= 1 && chgv == 0) break;                  // exact fixed point
    }
}

// ---------------------------------------------------------------------------
extern "C" void kernel_launch(void* const* d_in, const int* in_sizes, int n_in,
                              void* d_out, int out_size) {
    const float* spikes = (const float*)d_in[0];
    const float* w      = (const float*)d_in[1];
    const float* vrev   = (const float*)d_in[2];
    float*       vtr    = (float*)d_out;

    const int n = in_sizes[1];                       // 500
    const int m = in_sizes[0] / n;                   // 50000

    const int nchunk = (m + LC - 1) / LC;            // 196
    const int nseg   = (m - 1 + LSEG - 1) / LSEG;    // 63
    const int total  = nseg * LSEG;                  // 50400

    rowdot_kernel<<<(m + 7) / 8, 256>>>(spikes, w, vrev, m, n);
    chains_kernel<<<nchunk, 32>>>(nchunk);
    carry_kernel<<<1, 1>>>(nchunk);
    combine_kernel<<<(total + 255) / 256, 256>>>(vtr, m, total);
    sweep_kernel<<<nseg, 32>>>(vtr, m);
}